// round 1
// baseline (speedup 1.0000x reference)
#include <cuda_runtime.h>
#include <math.h>
#include <stdint.h>

#define NVAR   100000
#define NCLS   400000
#define NEDG   600000
#define HDIM   128
#define NSTEPS 9

// ---------------- scratch (device globals: sanctioned, no cudaMalloc) ----------------
__device__ float g_hv[NVAR * HDIM];
__device__ float g_cv[NVAR * HDIM];
__device__ float g_hc[NCLS * HDIM];
__device__ float g_cc[NCLS * HDIM];
__device__ float g_t1[NCLS * HDIM];
__device__ float g_t2[NCLS * HDIM];
__device__ float g_m [NCLS * HDIM];
__device__ float g_G [NCLS * 4 * HDIM];   // LSTM gate buffer [N, 512]
__device__ float g_z [NCLS];              // gate logits
__device__ float    g_red[HDIM];          // attention readout accumulator
__device__ float    g_sum;                // softmax denominator
__device__ unsigned g_maxu;               // ordered-uint max for softmax

// ---------------- helpers ----------------
__device__ __forceinline__ unsigned f2ord(float f) {
    unsigned b = __float_as_uint(f);
    return (b & 0x80000000u) ? ~b : (b | 0x80000000u);
}
__device__ __forceinline__ float ord2f(unsigned u) {
    unsigned b = (u & 0x80000000u) ? (u ^ 0x80000000u) : ~u;
    return __uint_as_float(b);
}
__device__ __forceinline__ float sigmoidf(float x) {
    return 1.0f / (1.0f + expf(-x));
}

// ---------------- init: h = c = embed[x] ----------------
__global__ void init_embed(const int* __restrict__ x, const float* __restrict__ embed,
                           float* __restrict__ h, float* __restrict__ c, int n) {
    int i = blockIdx.x * blockDim.x + threadIdx.x;
    if (i >= n * HDIM) return;
    int node = i >> 7, col = i & 127;
    float v = embed[x[node] * HDIM + col];
    h[i] = v;
    c[i] = v;
}

// ---------------- GEMM: Y[N,NOUT] = act( X[N,KTOT] @ W[NOUT,KTOT]^T + b ) ----------------
// X/W are (optionally) split at k=128 into two pointers (for the LSTM concat-K case).
// Tile 128x128, K-chunk 32, 256 threads, 8x8 microtile with strided row/col mapping
// (row = ty+16i, col = tx+16j) -> conflict-free smem loads with stride 33.
template <int RELU>
__global__ void __launch_bounds__(256, 2)
gemm_k(const float* __restrict__ X1, const float* __restrict__ X2,
       const float* __restrict__ W1, const float* __restrict__ W2,
       const float* __restrict__ B1, const float* __restrict__ B2,
       float* __restrict__ Y, int N, int NOUT, int KTOT)
{
    __shared__ float Xs[128][33];
    __shared__ float Ws[128][33];

    const int tid  = threadIdx.x;
    const int tx   = tid & 15;
    const int ty   = tid >> 4;
    const int row0 = blockIdx.x << 7;
    const int col0 = blockIdx.y << 7;

    float acc[8][8];
#pragma unroll
    for (int i = 0; i < 8; i++)
#pragma unroll
        for (int j = 0; j < 8; j++) acc[i][j] = 0.f;

    for (int kc = 0; kc < KTOT; kc += 32) {
        // load 128x32 tiles of X and W (transposed operand handling via row pointers)
#pragma unroll
        for (int it = 0; it < 4; it++) {
            int idx = it * 256 + tid;
            int r   = idx >> 3;     // 0..127
            int c4  = idx & 7;      // 0..7 (float4 within 32-wide k-chunk)
            int gk  = kc + c4 * 4;

            int grow = row0 + r;
            float4 xv = make_float4(0.f, 0.f, 0.f, 0.f);
            if (grow < N) {
                const float* xp = (gk < 128) ? (X1 + (size_t)grow * 128 + gk)
                                             : (X2 + (size_t)grow * 128 + (gk - 128));
                xv = *(const float4*)xp;
            }
            Xs[r][c4 * 4 + 0] = xv.x;
            Xs[r][c4 * 4 + 1] = xv.y;
            Xs[r][c4 * 4 + 2] = xv.z;
            Xs[r][c4 * 4 + 3] = xv.w;

            int gcol = col0 + r;   // always < NOUT (grid.y = NOUT/128)
            const float* wp = (gk < 128) ? (W1 + (size_t)gcol * 128 + gk)
                                         : (W2 + (size_t)gcol * 128 + (gk - 128));
            float4 wv = *(const float4*)wp;
            Ws[r][c4 * 4 + 0] = wv.x;
            Ws[r][c4 * 4 + 1] = wv.y;
            Ws[r][c4 * 4 + 2] = wv.z;
            Ws[r][c4 * 4 + 3] = wv.w;
        }
        __syncthreads();

#pragma unroll 8
        for (int k = 0; k < 32; k++) {
            float a[8], b[8];
#pragma unroll
            for (int i = 0; i < 8; i++) a[i] = Xs[ty + 16 * i][k];
#pragma unroll
            for (int j = 0; j < 8; j++) b[j] = Ws[tx + 16 * j][k];
#pragma unroll
            for (int i = 0; i < 8; i++)
#pragma unroll
                for (int j = 0; j < 8; j++)
                    acc[i][j] = fmaf(a[i], b[j], acc[i][j]);
        }
        __syncthreads();
    }

#pragma unroll
    for (int j = 0; j < 8; j++) {
        int col = col0 + tx + 16 * j;
        float bias = B1[col] + (B2 ? B2[col] : 0.f);
#pragma unroll
        for (int i = 0; i < 8; i++) {
            int row = row0 + ty + 16 * i;
            if (row < N) {
                float v = acc[i][j] + bias;
                if (RELU) v = fmaxf(v, 0.f);
                Y[(size_t)row * NOUT + col] = v;
            }
        }
    }
}

// ---------------- edge scatter-add: m[dst] += t[src] ----------------
__global__ void scatter_add(const float* __restrict__ t, const int* __restrict__ src,
                            const int* __restrict__ dst, float* __restrict__ m, int E)
{
    int idx  = blockIdx.x * blockDim.x + threadIdx.x;
    int e    = idx >> 5;
    int lane = idx & 31;
    if (e >= E) return;
    int s = src[e], d = dst[e];
    float4 v = *(const float4*)(t + (size_t)s * HDIM + lane * 4);
    float* out = m + (size_t)d * HDIM + lane * 4;
    atomicAdd(out + 0, v.x);
    atomicAdd(out + 1, v.y);
    atomicAdd(out + 2, v.z);
    atomicAdd(out + 3, v.w);
}

// ---------------- LSTM pointwise (i,f,g,o split; relu on new cell AFTER h) ----------------
__global__ void lstm_pw(const float* __restrict__ G, float* __restrict__ h,
                        float* __restrict__ c, int n)
{
    int idx = blockIdx.x * blockDim.x + threadIdx.x;
    if (idx >= n * HDIM) return;
    int row = idx >> 7, col = idx & 127;
    const float* g = G + (size_t)row * 512;
    float gi = g[col];
    float gf = g[col + 128];
    float gg = g[col + 256];
    float go = g[col + 384];
    float cn = sigmoidf(gf) * c[idx] + sigmoidf(gi) * tanhf(gg);
    h[idx] = sigmoidf(go) * tanhf(cn);
    c[idx] = fmaxf(cn, 0.f);
}

// ---------------- attention pooling ----------------
__global__ void pool_reset(unsigned* maxu, float* sum, float* red) {
    if (threadIdx.x == 0) { *maxu = 0u; *sum = 0.f; }
    if (threadIdx.x < HDIM) red[threadIdx.x] = 0.f;
}

__global__ void gate_logits(const float* __restrict__ cc, const float* __restrict__ gW,
                            const float* __restrict__ gb, float* __restrict__ z,
                            unsigned* __restrict__ maxu, int n)
{
    __shared__ float smax[8];
    int gw   = (blockIdx.x * blockDim.x + threadIdx.x) >> 5;   // clause id
    int lane = threadIdx.x & 31;
    int wid  = threadIdx.x >> 5;
    float myz = -1e30f;
    if (gw < n) {
        float4 a = *(const float4*)(cc + (size_t)gw * HDIM + lane * 4);
        float4 b = *(const float4*)(gW + lane * 4);
        float p = a.x * b.x + a.y * b.y + a.z * b.z + a.w * b.w;
        p += __shfl_down_sync(0xFFFFFFFFu, p, 16);
        p += __shfl_down_sync(0xFFFFFFFFu, p, 8);
        p += __shfl_down_sync(0xFFFFFFFFu, p, 4);
        p += __shfl_down_sync(0xFFFFFFFFu, p, 2);
        p += __shfl_down_sync(0xFFFFFFFFu, p, 1);
        if (lane == 0) {
            myz = p + gb[0];
            z[gw] = myz;
        }
    }
    if (lane == 0) smax[wid] = myz;
    __syncthreads();
    if (threadIdx.x == 0) {
        float mx = smax[0];
#pragma unroll
        for (int w = 1; w < 8; w++) mx = fmaxf(mx, smax[w]);
        atomicMax(maxu, f2ord(mx));
    }
}

__global__ void softmax_accum(const float* __restrict__ cc, const float* __restrict__ z,
                              const unsigned* __restrict__ maxu,
                              float* __restrict__ sum, float* __restrict__ red, int n)
{
    int t = threadIdx.x;             // 128 threads = one feature each
    float zmax = ord2f(*maxu);
    int c0 = blockIdx.x * 64;
    float acc = 0.f, wsum = 0.f;
    for (int i = 0; i < 64; i++) {
        int c = c0 + i;
        if (c >= n) break;
        float w = expf(z[c] - zmax);
        acc  += w * cc[(size_t)c * HDIM + t];
        wsum += w;
    }
    atomicAdd(&red[t], acc);
    if (t == 0) atomicAdd(sum, wsum);
}

__global__ void final_mlp(const float* __restrict__ red, const float* __restrict__ sum,
                          const float* __restrict__ mW1, const float* __restrict__ mb1,
                          const float* __restrict__ mW2, const float* __restrict__ mb2,
                          const float* __restrict__ mW3, const float* __restrict__ mb3,
                          float* __restrict__ out)
{
    __shared__ float x0[HDIM], x1[HDIM], x2[HDIM];
    int t = threadIdx.x;
    x0[t] = red[t] / (*sum);
    __syncthreads();
    {
        float a = mb1[t];
        for (int k = 0; k < HDIM; k++) a = fmaf(x0[k], mW1[t * HDIM + k], a);
        x1[t] = fmaxf(a, 0.f);
    }
    __syncthreads();
    {
        float a = mb2[t];
        for (int k = 0; k < HDIM; k++) a = fmaf(x1[k], mW2[t * HDIM + k], a);
        x2[t] = fmaxf(a, 0.f);
    }
    __syncthreads();
    if (t < 2) {
        float a = mb3[t];
        for (int k = 0; k < HDIM; k++) a = fmaf(x2[k], mW3[t * HDIM + k], a);
        out[t] = a;
    }
}

// ---------------- host orchestration ----------------
static void mlp3(const float* x, int n,
                 const float* W1, const float* b1,
                 const float* W2, const float* b2,
                 const float* W3, const float* b3,
                 float* t1, float* t2)
{
    dim3 grid((n + 127) / 128, 1);
    gemm_k<1><<<grid, 256>>>(x,  nullptr, W1, nullptr, b1, nullptr, t1, n, 128, 128);
    gemm_k<1><<<grid, 256>>>(t1, nullptr, W2, nullptr, b2, nullptr, t2, n, 128, 128);
    gemm_k<1><<<grid, 256>>>(t2, nullptr, W3, nullptr, b3, nullptr, t1, n, 128, 128);
}

extern "C" void kernel_launch(void* const* d_in, const int* in_sizes, int n_in,
                              void* d_out, int out_size)
{
    const int*   var_x    = (const int*)  d_in[0];
    const int*   clause_x = (const int*)  d_in[1];
    const int*   pos_src  = (const int*)  d_in[2];
    const int*   pos_dst  = (const int*)  d_in[3];
    const int*   neg_src  = (const int*)  d_in[4];
    const int*   neg_dst  = (const int*)  d_in[5];
    const int*   posr_src = (const int*)  d_in[6];
    const int*   posr_dst = (const int*)  d_in[7];
    const int*   negr_src = (const int*)  d_in[8];
    const int*   negr_dst = (const int*)  d_in[9];
    const float* embed    = (const float*)d_in[10];
    const float* eW1      = (const float*)d_in[11];
    const float* eb1      = (const float*)d_in[12];
    const float* eW2      = (const float*)d_in[13];
    const float* eb2      = (const float*)d_in[14];
    const float* eW3      = (const float*)d_in[15];
    const float* eb3      = (const float*)d_in[16];
    const float* Wih      = (const float*)d_in[17];
    const float* Whh      = (const float*)d_in[18];
    const float* bih      = (const float*)d_in[19];
    const float* bhh      = (const float*)d_in[20];
    const float* gW       = (const float*)d_in[21];
    const float* gb       = (const float*)d_in[22];
    const float* mW1      = (const float*)d_in[23];
    const float* mb1      = (const float*)d_in[24];
    const float* mW2      = (const float*)d_in[25];
    const float* mb2      = (const float*)d_in[26];
    const float* mW3      = (const float*)d_in[27];
    const float* mb3      = (const float*)d_in[28];
    float* out = (float*)d_out;

    float *hv, *cv, *hc, *cc, *t1, *t2, *m, *G, *z, *red, *sum;
    unsigned* maxu;
    cudaGetSymbolAddress((void**)&hv,   g_hv);
    cudaGetSymbolAddress((void**)&cv,   g_cv);
    cudaGetSymbolAddress((void**)&hc,   g_hc);
    cudaGetSymbolAddress((void**)&cc,   g_cc);
    cudaGetSymbolAddress((void**)&t1,   g_t1);
    cudaGetSymbolAddress((void**)&t2,   g_t2);
    cudaGetSymbolAddress((void**)&m,    g_m);
    cudaGetSymbolAddress((void**)&G,    g_G);
    cudaGetSymbolAddress((void**)&z,    g_z);
    cudaGetSymbolAddress((void**)&red,  g_red);
    cudaGetSymbolAddress((void**)&sum,  g_sum);
    cudaGetSymbolAddress((void**)&maxu, g_maxu);

    init_embed<<<(NVAR * HDIM + 255) / 256, 256>>>(var_x,    embed, hv, cv, NVAR);
    init_embed<<<(NCLS * HDIM + 255) / 256, 256>>>(clause_x, embed, hc, cc, NCLS);

    const int HH = HDIM * HDIM;                     // 16384
    const int scat_blocks = (NEDG * 32 + 255) / 256; // 75000

    for (int s = 0; s < NSTEPS; s++) {
        // ---- relation 0: var -> clause (etypes 0: pos, 1: neg) ----
        mlp3(cv, NVAR, eW1 + 0 * HH, eb1 + 0 * HDIM,
                       eW2 + 0 * HH, eb2 + 0 * HDIM,
                       eW3 + 0 * HH, eb3 + 0 * HDIM, t1, t2);
        cudaMemsetAsync(m, 0, (size_t)NCLS * HDIM * sizeof(float));
        scatter_add<<<scat_blocks, 256>>>(t1, pos_src, pos_dst, m, NEDG);

        mlp3(cv, NVAR, eW1 + 1 * HH, eb1 + 1 * HDIM,
                       eW2 + 1 * HH, eb2 + 1 * HDIM,
                       eW3 + 1 * HH, eb3 + 1 * HDIM, t1, t2);
        scatter_add<<<scat_blocks, 256>>>(t1, neg_src, neg_dst, m, NEDG);

        {   // clause LSTM: G = [m|h_c] @ [Wih0|Whh0]^T + bih0 + bhh0
            dim3 grid((NCLS + 127) / 128, 4);
            gemm_k<0><<<grid, 256>>>(m, hc, Wih, Whh, bih, bhh, G, NCLS, 512, 256);
        }
        lstm_pw<<<(NCLS * HDIM + 255) / 256, 256>>>(G, hc, cc, NCLS);

        // ---- relation 1: clause -> var (etypes 2: pos_r, 3: neg_r) ----
        mlp3(cc, NCLS, eW1 + 2 * HH, eb1 + 2 * HDIM,
                       eW2 + 2 * HH, eb2 + 2 * HDIM,
                       eW3 + 2 * HH, eb3 + 2 * HDIM, t1, t2);
        cudaMemsetAsync(m, 0, (size_t)NVAR * HDIM * sizeof(float));
        scatter_add<<<scat_blocks, 256>>>(t1, posr_src, posr_dst, m, NEDG);

        mlp3(cc, NCLS, eW1 + 3 * HH, eb1 + 3 * HDIM,
                       eW2 + 3 * HH, eb2 + 3 * HDIM,
                       eW3 + 3 * HH, eb3 + 3 * HDIM, t1, t2);
        scatter_add<<<scat_blocks, 256>>>(t1, negr_src, negr_dst, m, NEDG);

        {   // var LSTM
            dim3 grid((NVAR + 127) / 128, 4);
            gemm_k<0><<<grid, 256>>>(m, hv, Wih + 512 * HDIM, Whh + 512 * HDIM,
                                     bih + 512, bhh + 512, G, NVAR, 512, 256);
        }
        lstm_pw<<<(NVAR * HDIM + 255) / 256, 256>>>(G, hv, cv, NVAR);
    }

    // ---- GlobalAttentionPooling over clause cell states + final MLP ----
    pool_reset<<<1, 128>>>(maxu, sum, red);
    gate_logits<<<(NCLS * 32 + 255) / 256, 256>>>(cc, gW, gb, z, maxu, NCLS);
    softmax_accum<<<(NCLS + 63) / 64, 128>>>(cc, z, maxu, sum, red, NCLS);
    final_mlp<<<1, 128>>>(red, sum, mW1, mb1, mW2, mb2, mW3, mb3, out);
}

// round 3
// speedup vs baseline: 1.6056x; 1.6056x over previous
#include <cuda_runtime.h>
#include <math.h>
#include <stdint.h>

#define NVAR   100000
#define NCLS   400000
#define NEDG   600000
#define HDIM   128
#define NSTEPS 9

// ---------------- scratch (device globals) ----------------
__device__ float g_hv[NVAR * HDIM];
__device__ float g_cv[NVAR * HDIM];
__device__ float g_hc[NCLS * HDIM];
__device__ float g_cc[NCLS * HDIM];
__device__ float g_t1[NCLS * HDIM];
__device__ float g_t2[NCLS * HDIM];
__device__ float g_m [NCLS * HDIM];
__device__ float g_G [NCLS * 4 * HDIM];
__device__ float g_z [NCLS];
__device__ float    g_red[HDIM];
__device__ float    g_sum;
__device__ unsigned g_maxu;

// ---------------- helpers ----------------
__device__ __forceinline__ unsigned f2ord(float f) {
    unsigned b = __float_as_uint(f);
    return (b & 0x80000000u) ? ~b : (b | 0x80000000u);
}
__device__ __forceinline__ float ord2f(unsigned u) {
    unsigned b = (u & 0x80000000u) ? (u ^ 0x80000000u) : ~u;
    return __uint_as_float(b);
}
__device__ __forceinline__ float sigmoidf(float x) { return 1.0f / (1.0f + expf(-x)); }

__device__ __forceinline__ uint32_t f2tf32(float f) {
    uint32_t o;
    asm("cvt.rna.tf32.f32 %0, %1;" : "=r"(o) : "f"(f));
    return o;
}

__device__ __forceinline__ void mma_tf32(float* c, const uint32_t* a, uint32_t b0, uint32_t b1) {
    asm volatile(
        "mma.sync.aligned.m16n8k8.row.col.f32.tf32.tf32.f32 "
        "{%0,%1,%2,%3}, {%4,%5,%6,%7}, {%8,%9}, {%0,%1,%2,%3};"
        : "+f"(c[0]), "+f"(c[1]), "+f"(c[2]), "+f"(c[3])
        : "r"(a[0]), "r"(a[1]), "r"(a[2]), "r"(a[3]), "r"(b0), "r"(b1));
}

// ---------------- init: h = c = embed[x] ----------------
__global__ void init_embed(const int* __restrict__ x, const float* __restrict__ embed,
                           float* __restrict__ h, float* __restrict__ c, int n) {
    int i = blockIdx.x * blockDim.x + threadIdx.x;
    if (i >= n * HDIM) return;
    int node = i >> 7, col = i & 127;
    float v = embed[x[node] * HDIM + col];
    h[i] = v;
    c[i] = v;
}

// ================= tf32 mma.sync GEMM: Y = act( X @ W^T + b ) =================
// 128x128 CTA tile, K chunks of 32. 8 warps in 4(m) x 2(n) grid; warp tile 32x64.
// X/W/B optionally split at k=128 (LSTM concat-K case).
// Smem stride 36 floats: conflict-free fragment loads (row*36%32 = row*4%32).
template <int RELU>
__global__ void __launch_bounds__(256)
gemm_mma(const float* __restrict__ X1, const float* __restrict__ X2,
         const float* __restrict__ W1, const float* __restrict__ W2,
         const float* __restrict__ B1, const float* __restrict__ B2,
         float* __restrict__ Y, int N, int NOUT, int KTOT)
{
    __shared__ float Xs[128][36];
    __shared__ float Ws[128][36];
    __shared__ float sbias[128];

    const int tid    = threadIdx.x;
    const int wid    = tid >> 5;
    const int lane   = tid & 31;
    const int warp_m = wid & 3;          // 4 warps down M (32 rows each)
    const int warp_n = wid >> 2;         // 2 warps across N (64 cols each)
    const int gid    = lane >> 2;        // groupID 0..7
    const int thid   = lane & 3;         // threadID-in-group 0..3
    const int row0   = blockIdx.x << 7;
    const int col0   = blockIdx.y << 7;

    if (tid < 128) {
        float b = B1[col0 + tid];
        if (B2) b += B2[col0 + tid];
        sbias[tid] = b;
    }

    float acc[2][8][4];
#pragma unroll
    for (int mt = 0; mt < 2; mt++)
#pragma unroll
        for (int nt = 0; nt < 8; nt++)
#pragma unroll
            for (int r = 0; r < 4; r++) acc[mt][nt][r] = 0.f;

    for (int kc = 0; kc < KTOT; kc += 32) {
        // ---- load 128x32 tiles of X and W, converting to tf32 in-flight ----
#pragma unroll
        for (int it = 0; it < 4; it++) {
            int idx = it * 256 + tid;     // 0..1023 float4 slots
            int r   = idx >> 3;           // 0..127
            int c4  = idx & 7;            // 0..7
            int gk  = kc + (c4 << 2);

            float4 xv = make_float4(0.f, 0.f, 0.f, 0.f);
            int grow = row0 + r;
            if (grow < N) {
                const float* xp = (gk < 128) ? (X1 + (size_t)grow * 128 + gk)
                                             : (X2 + (size_t)grow * 128 + (gk - 128));
                xv = *(const float4*)xp;
            }
            Xs[r][c4 * 4 + 0] = __uint_as_float(f2tf32(xv.x));
            Xs[r][c4 * 4 + 1] = __uint_as_float(f2tf32(xv.y));
            Xs[r][c4 * 4 + 2] = __uint_as_float(f2tf32(xv.z));
            Xs[r][c4 * 4 + 3] = __uint_as_float(f2tf32(xv.w));

            int gcol = col0 + r;          // always < NOUT
            const float* wp = (gk < 128) ? (W1 + (size_t)gcol * 128 + gk)
                                         : (W2 + (size_t)gcol * 128 + (gk - 128));
            float4 wv = *(const float4*)wp;
            Ws[r][c4 * 4 + 0] = __uint_as_float(f2tf32(wv.x));
            Ws[r][c4 * 4 + 1] = __uint_as_float(f2tf32(wv.y));
            Ws[r][c4 * 4 + 2] = __uint_as_float(f2tf32(wv.z));
            Ws[r][c4 * 4 + 3] = __uint_as_float(f2tf32(wv.w));
        }
        __syncthreads();

        // ---- 4 k-steps of m16n8k8 ----
#pragma unroll
        for (int ks = 0; ks < 4; ks++) {
            const int kb = ks * 8;
            uint32_t a[2][4];
#pragma unroll
            for (int mt = 0; mt < 2; mt++) {
                int rr = warp_m * 32 + mt * 16 + gid;
                a[mt][0] = __float_as_uint(Xs[rr    ][kb + thid    ]);
                a[mt][1] = __float_as_uint(Xs[rr + 8][kb + thid    ]);
                a[mt][2] = __float_as_uint(Xs[rr    ][kb + thid + 4]);
                a[mt][3] = __float_as_uint(Xs[rr + 8][kb + thid + 4]);
            }
#pragma unroll
            for (int nt = 0; nt < 8; nt++) {
                int cc_ = warp_n * 64 + nt * 8 + gid;
                uint32_t b0 = __float_as_uint(Ws[cc_][kb + thid    ]);
                uint32_t b1 = __float_as_uint(Ws[cc_][kb + thid + 4]);
                mma_tf32(acc[0][nt], a[0], b0, b1);
                mma_tf32(acc[1][nt], a[1], b0, b1);
            }
        }
        __syncthreads();
    }

    // ---- epilogue: bias (+ReLU), float2 stores ----
#pragma unroll
    for (int mt = 0; mt < 2; mt++) {
        int rbase = row0 + warp_m * 32 + mt * 16 + gid;
#pragma unroll
        for (int nt = 0; nt < 8; nt++) {
            int colL = warp_n * 64 + nt * 8 + thid * 2;
            int col  = col0 + colL;
            float b0 = sbias[colL], b1 = sbias[colL + 1];
            float2 v0, v1;
            v0.x = acc[mt][nt][0] + b0;  v0.y = acc[mt][nt][1] + b1;
            v1.x = acc[mt][nt][2] + b0;  v1.y = acc[mt][nt][3] + b1;
            if (RELU) {
                v0.x = fmaxf(v0.x, 0.f); v0.y = fmaxf(v0.y, 0.f);
                v1.x = fmaxf(v1.x, 0.f); v1.y = fmaxf(v1.y, 0.f);
            }
            if (rbase < N)     *(float2*)(Y + (size_t)rbase * NOUT + col)       = v0;
            if (rbase + 8 < N) *(float2*)(Y + (size_t)(rbase + 8) * NOUT + col) = v1;
        }
    }
}

// ---------------- edge scatter-add: m[dst] += t[src] ----------------
__global__ void scatter_add(const float* __restrict__ t, const int* __restrict__ src,
                            const int* __restrict__ dst, float* __restrict__ m, int E)
{
    int idx  = blockIdx.x * blockDim.x + threadIdx.x;
    int e    = idx >> 5;
    int lane = idx & 31;
    if (e >= E) return;
    int s = src[e], d = dst[e];
    float4 v = *(const float4*)(t + (size_t)s * HDIM + lane * 4);
    float* out = m + (size_t)d * HDIM + lane * 4;
    atomicAdd(out + 0, v.x);
    atomicAdd(out + 1, v.y);
    atomicAdd(out + 2, v.z);
    atomicAdd(out + 3, v.w);
}

// ---------------- LSTM pointwise ----------------
__global__ void lstm_pw(const float* __restrict__ G, float* __restrict__ h,
                        float* __restrict__ c, int n)
{
    int idx = blockIdx.x * blockDim.x + threadIdx.x;
    if (idx >= n * HDIM) return;
    int row = idx >> 7, col = idx & 127;
    const float* g = G + (size_t)row * 512;
    float gi = g[col];
    float gf = g[col + 128];
    float gg = g[col + 256];
    float go = g[col + 384];
    float cn = sigmoidf(gf) * c[idx] + sigmoidf(gi) * tanhf(gg);
    h[idx] = sigmoidf(go) * tanhf(cn);
    c[idx] = fmaxf(cn, 0.f);
}

// ---------------- attention pooling ----------------
__global__ void pool_reset(unsigned* maxu, float* sum, float* red) {
    if (threadIdx.x == 0) { *maxu = 0u; *sum = 0.f; }
    if (threadIdx.x < HDIM) red[threadIdx.x] = 0.f;
}

__global__ void gate_logits(const float* __restrict__ cc, const float* __restrict__ gW,
                            const float* __restrict__ gb, float* __restrict__ z,
                            unsigned* __restrict__ maxu, int n)
{
    __shared__ float smax[8];
    int gw   = (blockIdx.x * blockDim.x + threadIdx.x) >> 5;
    int lane = threadIdx.x & 31;
    int wid  = threadIdx.x >> 5;
    float myz = -1e30f;
    if (gw < n) {
        float4 a = *(const float4*)(cc + (size_t)gw * HDIM + lane * 4);
        float4 b = *(const float4*)(gW + lane * 4);
        float p = a.x * b.x + a.y * b.y + a.z * b.z + a.w * b.w;
        p += __shfl_down_sync(0xFFFFFFFFu, p, 16);
        p += __shfl_down_sync(0xFFFFFFFFu, p, 8);
        p += __shfl_down_sync(0xFFFFFFFFu, p, 4);
        p += __shfl_down_sync(0xFFFFFFFFu, p, 2);
        p += __shfl_down_sync(0xFFFFFFFFu, p, 1);
        if (lane == 0) {
            myz = p + gb[0];
            z[gw] = myz;
        }
    }
    if (lane == 0) smax[wid] = myz;
    __syncthreads();
    if (threadIdx.x == 0) {
        float mx = smax[0];
#pragma unroll
        for (int w = 1; w < 8; w++) mx = fmaxf(mx, smax[w]);
        atomicMax(maxu, f2ord(mx));
    }
}

__global__ void softmax_accum(const float* __restrict__ cc, const float* __restrict__ z,
                              const unsigned* __restrict__ maxu,
                              float* __restrict__ sum, float* __restrict__ red, int n)
{
    int t = threadIdx.x;
    float zmax = ord2f(*maxu);
    int c0 = blockIdx.x * 64;
    float acc = 0.f, wsum = 0.f;
    for (int i = 0; i < 64; i++) {
        int c = c0 + i;
        if (c >= n) break;
        float w = expf(z[c] - zmax);
        acc  += w * cc[(size_t)c * HDIM + t];
        wsum += w;
    }
    atomicAdd(&red[t], acc);
    if (t == 0) atomicAdd(sum, wsum);
}

__global__ void final_mlp(const float* __restrict__ red, const float* __restrict__ sum,
                          const float* __restrict__ mW1, const float* __restrict__ mb1,
                          const float* __restrict__ mW2, const float* __restrict__ mb2,
                          const float* __restrict__ mW3, const float* __restrict__ mb3,
                          float* __restrict__ out)
{
    __shared__ float x0[HDIM], x1[HDIM], x2[HDIM];
    int t = threadIdx.x;
    x0[t] = red[t] / (*sum);
    __syncthreads();
    {
        float a = mb1[t];
        for (int k = 0; k < HDIM; k++) a = fmaf(x0[k], mW1[t * HDIM + k], a);
        x1[t] = fmaxf(a, 0.f);
    }
    __syncthreads();
    {
        float a = mb2[t];
        for (int k = 0; k < HDIM; k++) a = fmaf(x1[k], mW2[t * HDIM + k], a);
        x2[t] = fmaxf(a, 0.f);
    }
    __syncthreads();
    if (t < 2) {
        float a = mb3[t];
        for (int k = 0; k < HDIM; k++) a = fmaf(x2[k], mW3[t * HDIM + k], a);
        out[t] = a;
    }
}

// ---------------- host orchestration ----------------
static void mlp3(const float* x, int n,
                 const float* W1, const float* b1,
                 const float* W2, const float* b2,
                 const float* W3, const float* b3,
                 float* t1, float* t2)
{
    dim3 grid((n + 127) / 128, 1);
    gemm_mma<1><<<grid, 256>>>(x,  nullptr, W1, nullptr, b1, nullptr, t1, n, 128, 128);
    gemm_mma<1><<<grid, 256>>>(t1, nullptr, W2, nullptr, b2, nullptr, t2, n, 128, 128);
    gemm_mma<1><<<grid, 256>>>(t2, nullptr, W3, nullptr, b3, nullptr, t1, n, 128, 128);
}

extern "C" void kernel_launch(void* const* d_in, const int* in_sizes, int n_in,
                              void* d_out, int out_size)
{
    const int*   var_x    = (const int*)  d_in[0];
    const int*   clause_x = (const int*)  d_in[1];
    const int*   pos_src  = (const int*)  d_in[2];
    const int*   pos_dst  = (const int*)  d_in[3];
    const int*   neg_src  = (const int*)  d_in[4];
    const int*   neg_dst  = (const int*)  d_in[5];
    const int*   posr_src = (const int*)  d_in[6];
    const int*   posr_dst = (const int*)  d_in[7];
    const int*   negr_src = (const int*)  d_in[8];
    const int*   negr_dst = (const int*)  d_in[9];
    const float* embed    = (const float*)d_in[10];
    const float* eW1      = (const float*)d_in[11];
    const float* eb1      = (const float*)d_in[12];
    const float* eW2      = (const float*)d_in[13];
    const float* eb2      = (const float*)d_in[14];
    const float* eW3      = (const float*)d_in[15];
    const float* eb3      = (const float*)d_in[16];
    const float* Wih      = (const float*)d_in[17];
    const float* Whh      = (const float*)d_in[18];
    const float* bih      = (const float*)d_in[19];
    const float* bhh      = (const float*)d_in[20];
    const float* gW       = (const float*)d_in[21];
    const float* gb       = (const float*)d_in[22];
    const float* mW1      = (const float*)d_in[23];
    const float* mb1      = (const float*)d_in[24];
    const float* mW2      = (const float*)d_in[25];
    const float* mb2      = (const float*)d_in[26];
    const float* mW3      = (const float*)d_in[27];
    const float* mb3      = (const float*)d_in[28];
    float* out = (float*)d_out;

    float *hv, *cv, *hc, *cc, *t1, *t2, *m, *G, *z, *red, *sum;
    unsigned* maxu;
    cudaGetSymbolAddress((void**)&hv,   g_hv);
    cudaGetSymbolAddress((void**)&cv,   g_cv);
    cudaGetSymbolAddress((void**)&hc,   g_hc);
    cudaGetSymbolAddress((void**)&cc,   g_cc);
    cudaGetSymbolAddress((void**)&t1,   g_t1);
    cudaGetSymbolAddress((void**)&t2,   g_t2);
    cudaGetSymbolAddress((void**)&m,    g_m);
    cudaGetSymbolAddress((void**)&G,    g_G);
    cudaGetSymbolAddress((void**)&z,    g_z);
    cudaGetSymbolAddress((void**)&red,  g_red);
    cudaGetSymbolAddress((void**)&sum,  g_sum);
    cudaGetSymbolAddress((void**)&maxu, g_maxu);

    init_embed<<<(NVAR * HDIM + 255) / 256, 256>>>(var_x,    embed, hv, cv, NVAR);
    init_embed<<<(NCLS * HDIM + 255) / 256, 256>>>(clause_x, embed, hc, cc, NCLS);

    const int HH = HDIM * HDIM;
    const int scat_blocks = (NEDG * 32 + 255) / 256;

    for (int s = 0; s < NSTEPS; s++) {
        // ---- relation 0: var -> clause (etypes 0 pos, 1 neg) ----
        mlp3(cv, NVAR, eW1 + 0 * HH, eb1 + 0 * HDIM,
                       eW2 + 0 * HH, eb2 + 0 * HDIM,
                       eW3 + 0 * HH, eb3 + 0 * HDIM, t1, t2);
        cudaMemsetAsync(m, 0, (size_t)NCLS * HDIM * sizeof(float));
        scatter_add<<<scat_blocks, 256>>>(t1, pos_src, pos_dst, m, NEDG);

        mlp3(cv, NVAR, eW1 + 1 * HH, eb1 + 1 * HDIM,
                       eW2 + 1 * HH, eb2 + 1 * HDIM,
                       eW3 + 1 * HH, eb3 + 1 * HDIM, t1, t2);
        scatter_add<<<scat_blocks, 256>>>(t1, neg_src, neg_dst, m, NEDG);

        {   // clause LSTM: G = [m|h_c] @ [Wih0|Whh0]^T + b
            dim3 grid((NCLS + 127) / 128, 4);
            gemm_mma<0><<<grid, 256>>>(m, hc, Wih, Whh, bih, bhh, G, NCLS, 512, 256);
        }
        lstm_pw<<<(NCLS * HDIM + 255) / 256, 256>>>(G, hc, cc, NCLS);

        // ---- relation 1: clause -> var (etypes 2 pos_r, 3 neg_r) ----
        mlp3(cc, NCLS, eW1 + 2 * HH, eb1 + 2 * HDIM,
                       eW2 + 2 * HH, eb2 + 2 * HDIM,
                       eW3 + 2 * HH, eb3 + 2 * HDIM, t1, t2);
        cudaMemsetAsync(m, 0, (size_t)NVAR * HDIM * sizeof(float));
        scatter_add<<<scat_blocks, 256>>>(t1, posr_src, posr_dst, m, NEDG);

        mlp3(cc, NCLS, eW1 + 3 * HH, eb1 + 3 * HDIM,
                       eW2 + 3 * HH, eb2 + 3 * HDIM,
                       eW3 + 3 * HH, eb3 + 3 * HDIM, t1, t2);
        scatter_add<<<scat_blocks, 256>>>(t1, negr_src, negr_dst, m, NEDG);

        {   // var LSTM
            dim3 grid((NVAR + 127) / 128, 4);
            gemm_mma<0><<<grid, 256>>>(m, hv, Wih + 512 * HDIM, Whh + 512 * HDIM,
                                       bih + 512, bhh + 512, G, NVAR, 512, 256);
        }
        lstm_pw<<<(NVAR * HDIM + 255) / 256, 256>>>(G, hv, cv, NVAR);
    }

    // ---- GlobalAttentionPooling + final MLP ----
    pool_reset<<<1, 128>>>(maxu, sum, red);
    gate_logits<<<(NCLS * 32 + 255) / 256, 256>>>(cc, gW, gb, z, maxu, NCLS);
    softmax_accum<<<(NCLS + 63) / 64, 128>>>(cc, z, maxu, sum, red, NCLS);
    final_mlp<<<1, 128>>>(red, sum, mW1, mb1, mW2, mb2, mW3, mb3, out);
}

// round 4
// speedup vs baseline: 2.4463x; 1.5236x over previous
#include <cuda_runtime.h>
#include <math.h>
#include <stdint.h>

#define NVAR   100000
#define NCLS   400000
#define NEDG   600000
#define HDIM   128
#define NSTEPS 9

// ---------------- scratch (device globals) ----------------
__device__ float g_hv[NVAR * HDIM];
__device__ float g_cv[NVAR * HDIM];
__device__ float g_hc[NCLS * HDIM];
__device__ float g_cc[NCLS * HDIM];
__device__ float g_t1[NCLS * HDIM];
__device__ float g_t2[NCLS * HDIM];
__device__ float g_m [NCLS * HDIM];
__device__ float g_G [NCLS * 4 * HDIM];
__device__ float g_z [NCLS];
__device__ float    g_red[HDIM];
__device__ float    g_sum;
__device__ unsigned g_maxu;
// pre-rounded (tf32) weights: eW1 | eW2 | eW3 | Wih | Whh
#define OFF_E1  0
#define OFF_E2  65536
#define OFF_E3  131072
#define OFF_WIH 196608
#define OFF_WHH 327680
__device__ float g_wr[458752];

// ---------------- helpers ----------------
__device__ __forceinline__ unsigned f2ord(float f) {
    unsigned b = __float_as_uint(f);
    return (b & 0x80000000u) ? ~b : (b | 0x80000000u);
}
__device__ __forceinline__ float ord2f(unsigned u) {
    unsigned b = (u & 0x80000000u) ? (u ^ 0x80000000u) : ~u;
    return __uint_as_float(b);
}
__device__ __forceinline__ float sigmoidf(float x) { return 1.0f / (1.0f + expf(-x)); }

__device__ __forceinline__ uint32_t f2tf32(float f) {
    uint32_t o;
    asm("cvt.rna.tf32.f32 %0, %1;" : "=r"(o) : "f"(f));
    return o;
}

__device__ __forceinline__ uint32_t smem_u32(const void* p) {
    uint32_t a;
    asm("{ .reg .u64 t; cvta.to.shared.u64 t, %1; cvt.u32.u64 %0, t; }" : "=r"(a) : "l"(p));
    return a;
}

__device__ __forceinline__ void cp_async16(uint32_t dst, const void* src, int srcbytes) {
    asm volatile("cp.async.cg.shared.global [%0], [%1], 16, %2;"
                 :: "r"(dst), "l"(src), "r"(srcbytes) : "memory");
}
__device__ __forceinline__ void cp_commit() {
    asm volatile("cp.async.commit_group;" ::: "memory");
}

__device__ __forceinline__ void mma_tf32(float* c, const uint32_t* a, uint32_t b0, uint32_t b1) {
    asm volatile(
        "mma.sync.aligned.m16n8k8.row.col.f32.tf32.tf32.f32 "
        "{%0,%1,%2,%3}, {%4,%5,%6,%7}, {%8,%9}, {%0,%1,%2,%3};"
        : "+f"(c[0]), "+f"(c[1]), "+f"(c[2]), "+f"(c[3])
        : "r"(a[0]), "r"(a[1]), "r"(a[2]), "r"(a[3]), "r"(b0), "r"(b1));
}

// ---------------- weight pre-rounding to tf32 ----------------
__global__ void round_tf32(const float* __restrict__ src, float* __restrict__ dst, int n) {
    int i = blockIdx.x * blockDim.x + threadIdx.x;
    if (i < n) dst[i] = __uint_as_float(f2tf32(src[i]));
}

// ---------------- init: h = c = embed[x] ----------------
__global__ void init_embed(const int* __restrict__ x, const float* __restrict__ embed,
                           float* __restrict__ h, float* __restrict__ c, int n) {
    int i = blockIdx.x * blockDim.x + threadIdx.x;
    if (i >= n * HDIM) return;
    int node = i >> 7, col = i & 127;
    float v = embed[x[node] * HDIM + col];
    h[i] = v;
    c[i] = v;
}

// ============ tf32 mma.sync GEMM, cp.async 2-stage pipeline ============
// Y = act( X @ W^T + b ). 128x128 CTA tile, K chunks of 32.
// W must be pre-rounded tf32 bits; X is fp32, rounded per A-fragment (cvt.rna).
// X/W/B optionally split at k=128 (LSTM concat-K case).
// Dynamic smem: Xs[2][128*36] | Ws[2][128*36] | sbias[128]  (stride 36: conflict-free)
template <int RELU>
__global__ void __launch_bounds__(256)
gemm_mma(const float* __restrict__ X1, const float* __restrict__ X2,
         const float* __restrict__ W1, const float* __restrict__ W2,
         const float* __restrict__ B1, const float* __restrict__ B2,
         float* __restrict__ Y, int N, int NOUT, int KTOT)
{
    extern __shared__ float sm[];
    float* Xs    = sm;               // 2 * 4608 floats
    float* Ws    = sm + 9216;        // 2 * 4608 floats
    float* sbias = sm + 18432;       // 128 floats

    const int tid    = threadIdx.x;
    const int wid    = tid >> 5;
    const int lane   = tid & 31;
    const int warp_m = wid & 3;
    const int warp_n = wid >> 2;
    const int gid    = lane >> 2;
    const int thid   = lane & 3;
    const int row0   = blockIdx.x << 7;
    const int col0   = blockIdx.y << 7;
    const int Q      = KTOT >> 5;

    const uint32_t xaddr = smem_u32(Xs);
    const uint32_t waddr = smem_u32(Ws);

    if (tid < 128) {
        float b = B1[col0 + tid];
        if (B2) b += B2[col0 + tid];
        sbias[tid] = b;
    }

    float acc[2][8][4];
#pragma unroll
    for (int mt = 0; mt < 2; mt++)
#pragma unroll
        for (int nt = 0; nt < 8; nt++)
#pragma unroll
            for (int r = 0; r < 4; r++) acc[mt][nt][r] = 0.f;

    auto issue = [&](int q, int st) {
        const int kc = q << 5;
        const uint32_t xb = xaddr + (uint32_t)st * 4608u * 4u;
        const uint32_t wb = waddr + (uint32_t)st * 4608u * 4u;
#pragma unroll
        for (int it = 0; it < 4; it++) {
            int idx = it * 256 + tid;          // 0..1023
            int r   = idx >> 3;                // 0..127
            int c4  = idx & 7;                 // 0..7
            int gk  = kc + (c4 << 2);
            uint32_t soff = (uint32_t)(r * 36 + c4 * 4) * 4u;
            // X (zero-fill OOB rows)
            {
                int grow = row0 + r;
                const float* xp = X1;
                int sz = 0;
                if (grow < N) {
                    xp = (gk < 128) ? (X1 + (size_t)grow * 128 + gk)
                                    : (X2 + (size_t)grow * 128 + (gk - 128));
                    sz = 16;
                }
                cp_async16(xb + soff, xp, sz);
            }
            // W (always in range)
            {
                int gcol = col0 + r;
                const float* wp = (gk < 128) ? (W1 + (size_t)gcol * 128 + gk)
                                             : (W2 + (size_t)gcol * 128 + (gk - 128));
                cp_async16(wb + soff, wp, 16);
            }
        }
        cp_commit();
    };

    issue(0, 0);
    for (int q = 0; q < Q; q++) {
        if (q + 1 < Q) {
            issue(q + 1, (q + 1) & 1);
            asm volatile("cp.async.wait_group 1;" ::: "memory");
        } else {
            asm volatile("cp.async.wait_group 0;" ::: "memory");
        }
        __syncthreads();

        const float* Xb = Xs + (q & 1) * 4608;
        const float* Wb = Ws + (q & 1) * 4608;
#pragma unroll
        for (int ks = 0; ks < 4; ks++) {
            const int kb = ks * 8;
            uint32_t a[2][4];
#pragma unroll
            for (int mt = 0; mt < 2; mt++) {
                int rr = warp_m * 32 + mt * 16 + gid;
                a[mt][0] = f2tf32(Xb[rr * 36 + kb + thid]);
                a[mt][1] = f2tf32(Xb[(rr + 8) * 36 + kb + thid]);
                a[mt][2] = f2tf32(Xb[rr * 36 + kb + thid + 4]);
                a[mt][3] = f2tf32(Xb[(rr + 8) * 36 + kb + thid + 4]);
            }
#pragma unroll
            for (int nt = 0; nt < 8; nt++) {
                int cc_ = warp_n * 64 + nt * 8 + gid;
                uint32_t b0 = __float_as_uint(Wb[cc_ * 36 + kb + thid]);
                uint32_t b1 = __float_as_uint(Wb[cc_ * 36 + kb + thid + 4]);
                mma_tf32(acc[0][nt], a[0], b0, b1);
                mma_tf32(acc[1][nt], a[1], b0, b1);
            }
        }
        __syncthreads();
    }

    // ---- epilogue: bias (+ReLU), float2 stores ----
#pragma unroll
    for (int mt = 0; mt < 2; mt++) {
        int rbase = row0 + warp_m * 32 + mt * 16 + gid;
#pragma unroll
        for (int nt = 0; nt < 8; nt++) {
            int colL = warp_n * 64 + nt * 8 + thid * 2;
            int col  = col0 + colL;
            float b0 = sbias[colL], b1 = sbias[colL + 1];
            float2 v0, v1;
            v0.x = acc[mt][nt][0] + b0;  v0.y = acc[mt][nt][1] + b1;
            v1.x = acc[mt][nt][2] + b0;  v1.y = acc[mt][nt][3] + b1;
            if (RELU) {
                v0.x = fmaxf(v0.x, 0.f); v0.y = fmaxf(v0.y, 0.f);
                v1.x = fmaxf(v1.x, 0.f); v1.y = fmaxf(v1.y, 0.f);
            }
            if (rbase < N)     *(float2*)(Y + (size_t)rbase * NOUT + col)       = v0;
            if (rbase + 8 < N) *(float2*)(Y + (size_t)(rbase + 8) * NOUT + col) = v1;
        }
    }
}

// ---------------- edge scatter-add: m[dst] += t[src] (vector red) ----------------
__global__ void scatter_add(const float* __restrict__ t, const int* __restrict__ src,
                            const int* __restrict__ dst, float* __restrict__ m, int E)
{
    int idx  = blockIdx.x * blockDim.x + threadIdx.x;
    int e    = idx >> 5;
    int lane = idx & 31;
    if (e >= E) return;
    int s = src[e], d = dst[e];
    float4 v = *(const float4*)(t + (size_t)s * HDIM + lane * 4);
    float* out = m + (size_t)d * HDIM + lane * 4;
    asm volatile("red.global.add.v4.f32 [%0], {%1, %2, %3, %4};"
                 :: "l"(out), "f"(v.x), "f"(v.y), "f"(v.z), "f"(v.w) : "memory");
}

// ---------------- LSTM pointwise ----------------
__global__ void lstm_pw(const float* __restrict__ G, float* __restrict__ h,
                        float* __restrict__ c, int n)
{
    int idx = blockIdx.x * blockDim.x + threadIdx.x;
    if (idx >= n * HDIM) return;
    int row = idx >> 7, col = idx & 127;
    const float* g = G + (size_t)row * 512;
    float gi = g[col];
    float gf = g[col + 128];
    float gg = g[col + 256];
    float go = g[col + 384];
    float cn = sigmoidf(gf) * c[idx] + sigmoidf(gi) * tanhf(gg);
    h[idx] = sigmoidf(go) * tanhf(cn);
    c[idx] = fmaxf(cn, 0.f);
}

// ---------------- attention pooling ----------------
__global__ void pool_reset(unsigned* maxu, float* sum, float* red) {
    if (threadIdx.x == 0) { *maxu = 0u; *sum = 0.f; }
    if (threadIdx.x < HDIM) red[threadIdx.x] = 0.f;
}

__global__ void gate_logits(const float* __restrict__ cc, const float* __restrict__ gW,
                            const float* __restrict__ gb, float* __restrict__ z,
                            unsigned* __restrict__ maxu, int n)
{
    __shared__ float smax[8];
    int gw   = (blockIdx.x * blockDim.x + threadIdx.x) >> 5;
    int lane = threadIdx.x & 31;
    int wid  = threadIdx.x >> 5;
    float myz = -1e30f;
    if (gw < n) {
        float4 a = *(const float4*)(cc + (size_t)gw * HDIM + lane * 4);
        float4 b = *(const float4*)(gW + lane * 4);
        float p = a.x * b.x + a.y * b.y + a.z * b.z + a.w * b.w;
        p += __shfl_down_sync(0xFFFFFFFFu, p, 16);
        p += __shfl_down_sync(0xFFFFFFFFu, p, 8);
        p += __shfl_down_sync(0xFFFFFFFFu, p, 4);
        p += __shfl_down_sync(0xFFFFFFFFu, p, 2);
        p += __shfl_down_sync(0xFFFFFFFFu, p, 1);
        if (lane == 0) {
            myz = p + gb[0];
            z[gw] = myz;
        }
    }
    if (lane == 0) smax[wid] = myz;
    __syncthreads();
    if (threadIdx.x == 0) {
        float mx = smax[0];
#pragma unroll
        for (int w = 1; w < 8; w++) mx = fmaxf(mx, smax[w]);
        atomicMax(maxu, f2ord(mx));
    }
}

__global__ void softmax_accum(const float* __restrict__ cc, const float* __restrict__ z,
                              const unsigned* __restrict__ maxu,
                              float* __restrict__ sum, float* __restrict__ red, int n)
{
    int t = threadIdx.x;
    float zmax = ord2f(*maxu);
    int c0 = blockIdx.x * 64;
    float acc = 0.f, wsum = 0.f;
    for (int i = 0; i < 64; i++) {
        int c = c0 + i;
        if (c >= n) break;
        float w = expf(z[c] - zmax);
        acc  += w * cc[(size_t)c * HDIM + t];
        wsum += w;
    }
    atomicAdd(&red[t], acc);
    if (t == 0) atomicAdd(sum, wsum);
}

__global__ void final_mlp(const float* __restrict__ red, const float* __restrict__ sum,
                          const float* __restrict__ mW1, const float* __restrict__ mb1,
                          const float* __restrict__ mW2, const float* __restrict__ mb2,
                          const float* __restrict__ mW3, const float* __restrict__ mb3,
                          float* __restrict__ out)
{
    __shared__ float x0[HDIM], x1[HDIM], x2[HDIM];
    int t = threadIdx.x;
    x0[t] = red[t] / (*sum);
    __syncthreads();
    {
        float a = mb1[t];
        for (int k = 0; k < HDIM; k++) a = fmaf(x0[k], mW1[t * HDIM + k], a);
        x1[t] = fmaxf(a, 0.f);
    }
    __syncthreads();
    {
        float a = mb2[t];
        for (int k = 0; k < HDIM; k++) a = fmaf(x1[k], mW2[t * HDIM + k], a);
        x2[t] = fmaxf(a, 0.f);
    }
    __syncthreads();
    if (t < 2) {
        float a = mb3[t];
        for (int k = 0; k < HDIM; k++) a = fmaf(x2[k], mW3[t * HDIM + k], a);
        out[t] = a;
    }
}

// ---------------- host orchestration ----------------
#define GEMM_SMEM ((2 * 4608 * 2 + 128) * 4)   // 74240 bytes

static void mlp3(const float* x, int n,
                 const float* W1, const float* b1,
                 const float* W2, const float* b2,
                 const float* W3, const float* b3,
                 float* t1, float* t2)
{
    dim3 grid((n + 127) / 128, 1);
    gemm_mma<1><<<grid, 256, GEMM_SMEM>>>(x,  nullptr, W1, nullptr, b1, nullptr, t1, n, 128, 128);
    gemm_mma<1><<<grid, 256, GEMM_SMEM>>>(t1, nullptr, W2, nullptr, b2, nullptr, t2, n, 128, 128);
    gemm_mma<1><<<grid, 256, GEMM_SMEM>>>(t2, nullptr, W3, nullptr, b3, nullptr, t1, n, 128, 128);
}

extern "C" void kernel_launch(void* const* d_in, const int* in_sizes, int n_in,
                              void* d_out, int out_size)
{
    const int*   var_x    = (const int*)  d_in[0];
    const int*   clause_x = (const int*)  d_in[1];
    const int*   pos_src  = (const int*)  d_in[2];
    const int*   pos_dst  = (const int*)  d_in[3];
    const int*   neg_src  = (const int*)  d_in[4];
    const int*   neg_dst  = (const int*)  d_in[5];
    const int*   posr_src = (const int*)  d_in[6];
    const int*   posr_dst = (const int*)  d_in[7];
    const int*   negr_src = (const int*)  d_in[8];
    const int*   negr_dst = (const int*)  d_in[9];
    const float* embed    = (const float*)d_in[10];
    const float* eW1      = (const float*)d_in[11];
    const float* eb1      = (const float*)d_in[12];
    const float* eW2      = (const float*)d_in[13];
    const float* eb2      = (const float*)d_in[14];
    const float* eW3      = (const float*)d_in[15];
    const float* eb3      = (const float*)d_in[16];
    const float* Wih      = (const float*)d_in[17];
    const float* Whh      = (const float*)d_in[18];
    const float* bih      = (const float*)d_in[19];
    const float* bhh      = (const float*)d_in[20];
    const float* gW       = (const float*)d_in[21];
    const float* gb       = (const float*)d_in[22];
    const float* mW1      = (const float*)d_in[23];
    const float* mb1      = (const float*)d_in[24];
    const float* mW2      = (const float*)d_in[25];
    const float* mb2      = (const float*)d_in[26];
    const float* mW3      = (const float*)d_in[27];
    const float* mb3      = (const float*)d_in[28];
    float* out = (float*)d_out;

    cudaFuncSetAttribute(gemm_mma<0>, cudaFuncAttributeMaxDynamicSharedMemorySize, GEMM_SMEM);
    cudaFuncSetAttribute(gemm_mma<1>, cudaFuncAttributeMaxDynamicSharedMemorySize, GEMM_SMEM);

    float *hv, *cv, *hc, *cc, *t1, *t2, *m, *G, *z, *red, *sum, *wr;
    unsigned* maxu;
    cudaGetSymbolAddress((void**)&hv,   g_hv);
    cudaGetSymbolAddress((void**)&cv,   g_cv);
    cudaGetSymbolAddress((void**)&hc,   g_hc);
    cudaGetSymbolAddress((void**)&cc,   g_cc);
    cudaGetSymbolAddress((void**)&t1,   g_t1);
    cudaGetSymbolAddress((void**)&t2,   g_t2);
    cudaGetSymbolAddress((void**)&m,    g_m);
    cudaGetSymbolAddress((void**)&G,    g_G);
    cudaGetSymbolAddress((void**)&z,    g_z);
    cudaGetSymbolAddress((void**)&red,  g_red);
    cudaGetSymbolAddress((void**)&sum,  g_sum);
    cudaGetSymbolAddress((void**)&maxu, g_maxu);
    cudaGetSymbolAddress((void**)&wr,   g_wr);

    // pre-round weights to tf32 (once per launch, deterministic)
    round_tf32<<<(65536 * 3 + 255) / 256, 256>>>(eW1, wr + OFF_E1, 65536 * 3 == 0 ? 0 : 65536);
    round_tf32<<<(65536 + 255) / 256, 256>>>(eW2, wr + OFF_E2, 65536);
    round_tf32<<<(65536 + 255) / 256, 256>>>(eW3, wr + OFF_E3, 65536);
    round_tf32<<<(131072 + 255) / 256, 256>>>(Wih, wr + OFF_WIH, 131072);
    round_tf32<<<(131072 + 255) / 256, 256>>>(Whh, wr + OFF_WHH, 131072);

    init_embed<<<(NVAR * HDIM + 255) / 256, 256>>>(var_x,    embed, hv, cv, NVAR);
    init_embed<<<(NCLS * HDIM + 255) / 256, 256>>>(clause_x, embed, hc, cc, NCLS);

    const int HH = HDIM * HDIM;
    const int scat_blocks = (NEDG * 32 + 255) / 256;

    const float* E1 = wr + OFF_E1;
    const float* E2 = wr + OFF_E2;
    const float* E3 = wr + OFF_E3;
    const float* WIH = wr + OFF_WIH;
    const float* WHH = wr + OFF_WHH;

    for (int s = 0; s < NSTEPS; s++) {
        // ---- relation 0: var -> clause (etypes 0 pos, 1 neg) ----
        mlp3(cv, NVAR, E1 + 0 * HH, eb1 + 0 * HDIM,
                       E2 + 0 * HH, eb2 + 0 * HDIM,
                       E3 + 0 * HH, eb3 + 0 * HDIM, t1, t2);
        cudaMemsetAsync(m, 0, (size_t)NCLS * HDIM * sizeof(float));
        scatter_add<<<scat_blocks, 256>>>(t1, pos_src, pos_dst, m, NEDG);

        mlp3(cv, NVAR, E1 + 1 * HH, eb1 + 1 * HDIM,
                       E2 + 1 * HH, eb2 + 1 * HDIM,
                       E3 + 1 * HH, eb3 + 1 * HDIM, t1, t2);
        scatter_add<<<scat_blocks, 256>>>(t1, neg_src, neg_dst, m, NEDG);

        {   // clause LSTM: G = [m|h_c] @ [Wih0|Whh0]^T + b
            dim3 grid((NCLS + 127) / 128, 4);
            gemm_mma<0><<<grid, 256, GEMM_SMEM>>>(m, hc, WIH, WHH, bih, bhh, G, NCLS, 512, 256);
        }
        lstm_pw<<<(NCLS * HDIM + 255) / 256, 256>>>(G, hc, cc, NCLS);

        // ---- relation 1: clause -> var (etypes 2 pos_r, 3 neg_r) ----
        mlp3(cc, NCLS, E1 + 2 * HH, eb1 + 2 * HDIM,
                       E2 + 2 * HH, eb2 + 2 * HDIM,
                       E3 + 2 * HH, eb3 + 2 * HDIM, t1, t2);
        cudaMemsetAsync(m, 0, (size_t)NVAR * HDIM * sizeof(float));
        scatter_add<<<scat_blocks, 256>>>(t1, posr_src, posr_dst, m, NEDG);

        mlp3(cc, NCLS, E1 + 3 * HH, eb1 + 3 * HDIM,
                       E2 + 3 * HH, eb2 + 3 * HDIM,
                       E3 + 3 * HH, eb3 + 3 * HDIM, t1, t2);
        scatter_add<<<scat_blocks, 256>>>(t1, negr_src, negr_dst, m, NEDG);

        {   // var LSTM
            dim3 grid((NVAR + 127) / 128, 4);
            gemm_mma<0><<<grid, 256, GEMM_SMEM>>>(m, hv, WIH + 512 * HDIM, WHH + 512 * HDIM,
                                                  bih + 512, bhh + 512, G, NVAR, 512, 256);
        }
        lstm_pw<<<(NVAR * HDIM + 255) / 256, 256>>>(G, hv, cv, NVAR);
    }

    // ---- GlobalAttentionPooling + final MLP ----
    pool_reset<<<1, 128>>>(maxu, sum, red);
    gate_logits<<<(NCLS * 32 + 255) / 256, 256>>>(cc, gW, gb, z, maxu, NCLS);
    softmax_accum<<<(NCLS + 63) / 64, 128>>>(cc, z, maxu, sum, red, NCLS);
    final_mlp<<<1, 128>>>(red, sum, mW1, mb1, mW2, mb2, mW3, mb3, out);
}